// round 13
// baseline (speedup 1.0000x reference)
#include <cuda_runtime.h>
#include <math.h>
#include <stdint.h>

#define BATCH 1024
#define N 200
#define H 128
#define K_TOP 8000
#define NBINS 4096
#define MAXCAND 1024
#define NCH 7

#define YT_STR 212
#define SB_STR 36
#define G2_STR 216

// float offsets into dynamic smem
#define YT_O   0
#define SB0_O  27136
#define SB1_O  34624
#define SW0_O  42112
#define SW1_O  46720
#define DINV_O 51328      // deg accumulates here, then becomes dinv in-place
#define U_O    51536
#define B1_O   51744
#define VACC_O 51872
#define SMEM_FLOATS 52000            // 208000 bytes

__device__ float g_w1t[NCH * H * 32];   // [c][h][kk], tf32-rounded

__device__ __forceinline__ float tf32r(float f) {
    unsigned u;
    asm("cvt.rna.tf32.f32 %0, %1;" : "=r"(u) : "f"(f));
    return __uint_as_float(u);
}
__device__ __forceinline__ unsigned fau(float f) { return __float_as_uint(f); }

__device__ __forceinline__ void mma8(float* c, const unsigned* a, unsigned b0, unsigned b1) {
    asm("mma.sync.aligned.m16n8k8.row.col.f32.tf32.tf32.f32 "
        "{%0,%1,%2,%3}, {%4,%5,%6,%7}, {%8,%9}, {%0,%1,%2,%3};"
        : "+f"(c[0]), "+f"(c[1]), "+f"(c[2]), "+f"(c[3])
        : "r"(a[0]), "r"(a[1]), "r"(a[2]), "r"(a[3]), "r"(b0), "r"(b1));
}
#define CPA16(d, s) asm volatile("cp.async.ca.shared.global [%0], [%1], 16;" :: "r"(d), "l"(s))
#define CPA_COMMIT() asm volatile("cp.async.commit_group;" ::: "memory")
#define CPA_WAIT1()  asm volatile("cp.async.wait_group 1;" ::: "memory")
#define CPA_WAIT0()  asm volatile("cp.async.wait_group 0;" ::: "memory")

// ============ tiny prep: W1^T chunk images (tf32-rounded) ============
__global__ void w1t_prep_kernel(const float* __restrict__ W1)
{
    int idx = blockIdx.x * 512 + threadIdx.x;      // 56 x 512 = 28672
    if (idx >= NCH * H * 32) return;
    int c = idx >> 12, r = idx & 4095;
    int h = r >> 5, kk = r & 31;
    int k = c * 32 + kk;
    g_w1t[idx] = (k < N) ? tf32r(W1[k * H + h]) : 0.f;
}

// ============ main: fully fused, 512 threads ============
extern __shared__ float sm[];

__global__ __launch_bounds__(512)
void main_kernel(const float* __restrict__ x,  const float* __restrict__ b1,
                 const float* __restrict__ W2, const float* __restrict__ b2,
                 float* __restrict__ out)
{
    const int b    = blockIdx.x;
    const int tid  = threadIdx.x;
    const int warp = tid >> 5;
    const int lane = tid & 31;
    const int g    = lane >> 2;       // 0..7
    const int tig  = lane & 3;        // 0..3
    const float* __restrict__ xb = x + (size_t)b * N * N;

    float* Yt     = sm + YT_O;
    float* dinv_s = sm + DINV_O;      // deg first, then dinv in place
    float* u_s    = sm + U_O;         // rowdot first, then u in place
    float* b1_s   = sm + B1_O;
    float* vacc   = sm + VACC_O;
    const unsigned shb = (unsigned)__cvta_generic_to_shared(sm);

    __shared__ float t_sh;
    __shared__ int binB_sh, r_sh, cnt_sh;

    // ---------------- Phase 0: exact k-th largest threshold ----------------
    // hist/cand overlay the (currently dead) Yt region
    {
        unsigned int* hist = (unsigned int*)(sm + YT_O);
        float*        cand = sm + YT_O + NBINS;

        for (int i = tid; i < NBINS; i += 512) hist[i] = 0u;
        __syncthreads();

        for (int e = tid; e < N * N; e += 512) {
            float vv = xb[e];
            int bin = (int)(vv * 4096.0f);
            bin = min(max(bin, 0), NBINS - 1);
            atomicAdd(&hist[bin], 1u);
        }
        __syncthreads();

        if (tid == 0) {
            int acc = 0, bsel = 0, r = 1;
            for (int bi = NBINS - 1; bi >= 0; --bi) {
                int nacc = acc + (int)hist[bi];
                if (nacc >= K_TOP) { bsel = bi; r = K_TOP - acc; break; }
                acc = nacc;
            }
            binB_sh = bsel; r_sh = r; cnt_sh = 0;
            t_sh = (float)bsel / 4096.0f;    // fallback, never expected
        }
        __syncthreads();

        const int binB = binB_sh;
        for (int e = tid; e < N * N; e += 512) {
            float vv = xb[e];
            int bin = (int)(vv * 4096.0f);
            bin = min(max(bin, 0), NBINS - 1);
            if (bin == binB) {
                int p = atomicAdd(&cnt_sh, 1);
                if (p < MAXCAND) cand[p] = vv;
            }
        }
        __syncthreads();

        {
            const int m = min(cnt_sh, MAXCAND);
            const int r = r_sh;
            for (int ci = tid; ci < m; ci += 512) {
                float vv = cand[ci];
                int gg = 0, eq = 0;
                for (int l = 0; l < m; ++l) {
                    float c = cand[l];
                    gg += (c > vv);
                    eq += (c == vv);
                }
                if (gg < r && gg + eq >= r) t_sh = vv;
            }
        }
        __syncthreads();
    }
    const float t = t_sh;

    if (tid < 208) { dinv_s[tid] = 0.f; u_s[tid] = 0.f; }
    if (tid < H)   { b1_s[tid] = b1[tid]; vacc[tid] = 0.f; }
    __syncthreads();

    // warp tiling: 8 m-tiles x 2 n-halves
    const int mw  = warp >> 1;        // 0..7 -> m-tile
    const int nh  = warp & 1;         // 0..1 -> n-half
    const int m0  = mw * 16;
    const int nlo = nh * 13;          // tiles nlo .. nlo+12 (guard nt<25)

    // ---------------- GEMM1: D1[h][i] = W1t @ X^T  (+ deg col-sums) --------
    auto stage1 = [&](int c, int buf) {
        const int kc = c * 32;
        const unsigned swd = shb + (buf ? SW1_O : SW0_O) * 4;
        const unsigned sbd = shb + (buf ? SB1_O : SB0_O) * 4;
        const float* wsrc = g_w1t + c * (H * 32);
        for (int idx = tid; idx < 1024; idx += 512) {       // W1t [128][32]
            int h = idx >> 3, q = idx & 7;
            CPA16(swd + h * 144 + q * 16, wsrc + h * 32 + q * 4);
        }
        if (c < NCH - 1) {                                   // x rows [200][32]
            for (int idx = tid; idx < 1600; idx += 512) {
                int i = idx >> 3, q = idx & 7;
                CPA16(sbd + i * 144 + q * 16, xb + i * N + kc + q * 4);
            }
        } else {                                             // last: [200][8]
            for (int idx = tid; idx < 400; idx += 512) {
                int i = idx >> 1, q = idx & 1;
                CPA16(sbd + i * 144 + q * 16, xb + i * N + kc + q * 4);
            }
        }
    };

    float C1[13][4];
    #pragma unroll
    for (int idx = 0; idx < 13; ++idx)
        #pragma unroll
        for (int q = 0; q < 4; ++q) C1[idx][q] = 0.f;

    stage1(0, 0);
    CPA_COMMIT();
    for (int c = 0; c < NCH; ++c) {
        if (c < NCH - 1) { stage1(c + 1, (c + 1) & 1); CPA_COMMIT(); CPA_WAIT1(); }
        else             { CPA_WAIT0(); }
        __syncthreads();
        const float* bs = sm + ((c & 1) ? SB1_O : SB0_O);
        const float* ws = sm + ((c & 1) ? SW1_O : SW0_O);
        const int kc  = c * 32;
        const int kw  = (c < NCH - 1) ? 32 : 8;
        const int kst = (c < NCH - 1) ? 4 : 1;
        for (int ks = 0; ks < kst; ++ks) {
            const int kk0 = ks * 8 + tig;
            unsigned a[4];
            {
                int r = m0 + g;
                a[0] = fau(ws[r * SB_STR + kk0]);
                a[1] = fau(ws[(r + 8) * SB_STR + kk0]);
                a[2] = fau(ws[r * SB_STR + kk0 + 4]);
                a[3] = fau(ws[(r + 8) * SB_STR + kk0 + 4]);
            }
            #pragma unroll
            for (int idx = 0; idx < 13; ++idx) {
                int nt = nlo + idx;
                if (nt < 25) {
                    int row = nt * 8 + g;
                    unsigned b0 = fau(bs[row * SB_STR + kk0]);
                    unsigned bq = fau(bs[row * SB_STR + kk0 + 4]);
                    mma8(C1[idx], a, b0, bq);
                }
            }
        }
        // deg: masked column sums of this col-block (cols kc..kc+kw)
        {
            const int colL = tid >> 4, part = tid & 15;   // 32 cols x 16 parts
            if (colL < kw) {
                float s = 0.f;
                const int i0 = part * 13;
                const int ie = min(i0 + 13, N);
                for (int i = i0; i < ie; ++i) {
                    float v = bs[i * SB_STR + colL];
                    s += (v >= t) ? v : 0.f;
                }
                s += __shfl_xor_sync(0xffffffffu, s, 1);
                s += __shfl_xor_sync(0xffffffffu, s, 2);
                s += __shfl_xor_sync(0xffffffffu, s, 4);
                s += __shfl_xor_sync(0xffffffffu, s, 8);
                if (part == 0) dinv_s[kc + colL] += s;
            }
        }
        __syncthreads();
    }

    // deg -> dinv (in place)
    if (tid < 208) dinv_s[tid] = (tid < N) ? rsqrtf(1.0f + dinv_s[tid]) : 0.f;
    __syncthreads();

    // Epilogue 1: Yt[h][i] = tf32(dinv_i * D1)
    {
        int h = m0 + g;
        #pragma unroll
        for (int idx = 0; idx < 13; ++idx) {
            int nt = nlo + idx;
            if (nt < 25) {
                int i0 = nt * 8 + tig * 2;
                float d0 = dinv_s[i0], d1 = dinv_s[i0 + 1];
                float2 lo = make_float2(tf32r(C1[idx][0] * d0), tf32r(C1[idx][1] * d1));
                float2 hi = make_float2(tf32r(C1[idx][2] * d0), tf32r(C1[idx][3] * d1));
                *(float2*)&Yt[h * YT_STR + i0]       = lo;
                *(float2*)&Yt[(h + 8) * YT_STR + i0] = hi;
            }
        }
    }

    // zero pad cols 200..207 of both GEMM2 staging buffers
    {
        int bf = tid >> 8, r = (tid >> 3) & 31, cq = tid & 7;
        sm[(bf ? SB1_O : SB0_O) + r * G2_STR + 200 + cq] = 0.f;
    }

    // ---------------- GEMM2: D2[h][j] = Yt @ (Am + I) ----------------
    auto stage2 = [&](int c, int buf) {
        const int kc = c * 32;
        const unsigned sbd = shb + (buf ? SB1_O : SB0_O) * 4;
        const int nrows = (c < NCH - 1) ? 32 : 8;
        for (int idx = tid; idx < nrows * 50; idx += 512) {
            int i = idx / 50, q = idx - i * 50;
            CPA16(sbd + i * (G2_STR * 4) + q * 16, xb + (size_t)(kc + i) * N + q * 4);
        }
    };

    float C2[13][4];
    #pragma unroll
    for (int idx = 0; idx < 13; ++idx)
        #pragma unroll
        for (int q = 0; q < 4; ++q) C2[idx][q] = 0.f;

    stage2(0, 0);
    CPA_COMMIT();
    for (int c = 0; c < NCH; ++c) {
        if (c < NCH - 1) { stage2(c + 1, (c + 1) & 1); CPA_COMMIT(); CPA_WAIT1(); }
        else             { CPA_WAIT0(); }
        __syncthreads();
        float* bs = sm + ((c & 1) ? SB1_O : SB0_O);
        const int kc    = c * 32;
        const int nrows = (c < NCH - 1) ? 32 : 8;
        // mask (>= t), add I on diagonal, tf32-round; accumulate u rowdots
        {
            const int il = tid >> 4, part = tid & 15;   // 32 rows x 16 parts
            float s = 0.f;
            if (il < nrows) {
                const int gi = kc + il;
                float* row = bs + il * G2_STR;
                const int j0 = part * 13;
                const int je = min(j0 + 13, N);
                for (int j = j0; j < je; ++j) {
                    float v = row[j];
                    v = (v >= t) ? v : 0.f;
                    if (j == gi) v += 1.0f;
                    v = tf32r(v);
                    row[j] = v;
                    s += v * dinv_s[j];
                }
            }
            s += __shfl_xor_sync(0xffffffffu, s, 1);
            s += __shfl_xor_sync(0xffffffffu, s, 2);
            s += __shfl_xor_sync(0xffffffffu, s, 4);
            s += __shfl_xor_sync(0xffffffffu, s, 8);
            if (part == 0 && il < nrows) u_s[kc + il] = s;
        }
        __syncthreads();
        const int kst = (c < NCH - 1) ? 4 : 1;
        for (int ks = 0; ks < kst; ++ks) {
            const int kk0 = ks * 8 + tig;
            unsigned a[4];
            {
                int r = m0 + g;
                a[0] = fau(Yt[r * YT_STR + kc + kk0]);
                a[1] = fau(Yt[(r + 8) * YT_STR + kc + kk0]);
                a[2] = fau(Yt[r * YT_STR + kc + kk0 + 4]);
                a[3] = fau(Yt[(r + 8) * YT_STR + kc + kk0 + 4]);
            }
            #pragma unroll
            for (int idx = 0; idx < 13; ++idx) {
                int nt = nlo + idx;
                if (nt < 25) {
                    int col = nt * 8 + g;
                    unsigned b0 = fau(bs[kk0 * G2_STR + col]);
                    unsigned bq = fau(bs[(kk0 + 4) * G2_STR + col]);
                    mma8(C2[idx], a, b0, bq);
                }
            }
        }
        __syncthreads();
    }

    // finalize u: u_j = dinv_j * rowdot_j (rowdot already includes +I term)
    if (tid < 208) u_s[tid] = (tid < N) ? dinv_s[tid] * u_s[tid] : 0.f;
    __syncthreads();

    // Epilogue 2: h1 = relu(dinv_j * D2 + b1_h); v_h += u_j * h1
    float sAcc[2] = {0.f, 0.f};
    {
        int h = m0 + g;
        float bl = b1_s[h], bh = b1_s[h + 8];
        #pragma unroll
        for (int idx = 0; idx < 13; ++idx) {
            int nt = nlo + idx;
            if (nt < 25) {
                int j0 = nt * 8 + tig * 2;
                int j1 = j0 + 1;
                float d0 = dinv_s[j0], d1 = dinv_s[j1];
                float u0 = u_s[j0],    u1 = u_s[j1];
                sAcc[0] += u0 * fmaxf(fmaf(d0, C2[idx][0], bl), 0.f)
                         + u1 * fmaxf(fmaf(d1, C2[idx][1], bl), 0.f);
                sAcc[1] += u0 * fmaxf(fmaf(d0, C2[idx][2], bh), 0.f)
                         + u1 * fmaxf(fmaf(d1, C2[idx][3], bh), 0.f);
            }
        }
    }
    #pragma unroll
    for (int hf = 0; hf < 2; ++hf) {
        float s = sAcc[hf];
        s += __shfl_xor_sync(0xffffffffu, s, 1);
        s += __shfl_xor_sync(0xffffffffu, s, 2);
        sAcc[hf] = s;
    }
    if (tig == 0) {
        atomicAdd(&vacc[m0 + g],     sAcc[0]);
        atomicAdd(&vacc[m0 + 8 + g], sAcc[1]);
    }
    __syncthreads();

    // fused final: out[b][h] = (1/N) * sum_f vacc[f] * W2[f][h] + b2[h]
    if (tid < H) {
        float acc = 0.f;
        #pragma unroll 8
        for (int f = 0; f < H; ++f)
            acc += vacc[f] * W2[f * H + tid];
        out[b * H + tid] = acc * (1.0f / (float)N) + b2[tid];
    }
}

extern "C" void kernel_launch(void* const* d_in, const int* in_sizes, int n_in,
                              void* d_out, int out_size)
{
    const float* x  = (const float*)d_in[0];
    // d_in[1] = adj : unused (overwritten by sparse(x,0.2) in the reference)
    const float* W1 = (const float*)d_in[2];
    const float* b1 = (const float*)d_in[3];
    const float* W2 = (const float*)d_in[4];
    const float* b2 = (const float*)d_in[5];
    float* out = (float*)d_out;

    cudaFuncSetAttribute(main_kernel,
                         cudaFuncAttributeMaxDynamicSharedMemorySize,
                         SMEM_FLOATS * (int)sizeof(float));

    w1t_prep_kernel<<<56, 512>>>(W1);                                   // launch 1
    main_kernel<<<BATCH, 512, SMEM_FLOATS * sizeof(float)>>>(x, b1, W2, b2, out);  // launch 2
}

// round 17
// speedup vs baseline: 1.3073x; 1.3073x over previous
#include <cuda_runtime.h>
#include <math.h>
#include <stdint.h>

#define BATCH 1024
#define N 200
#define H 128
#define K_TOP 8000
#define NBINS 4096
#define MAXCAND 1024
#define NCH 13              // k-chunks of 16 (last = 8)

#define YT_STR 212
#define S1_STR 20
#define G2_STR 216

// float offsets into dynamic smem (per half-CTA, ~97 KB total)
#define YT_O   0            // 64 x 212 = 13568
#define SB0_O  13568        // 4000 (max(200x20, 16x216))
#define SB1_O  17568        // 4000
#define SW0_O  21568        // 1280 (64x20)
#define SW1_O  22848        // 1280
#define DINV_O 24128        // 208
#define U_O    24336        // 208
#define B1_O   24544        // 64
#define VACC_O 24608        // 64
#define SMEM_FLOATS 24672   // 98688 bytes

__device__ float g_t[BATCH];
__device__ float g_w1t[NCH * 2 * 64 * 16];   // [c][hh][hl][kk], tf32-rounded
__device__ float g_v[BATCH * H];

__device__ __forceinline__ float tf32r(float f) {
    unsigned u;
    asm("cvt.rna.tf32.f32 %0, %1;" : "=r"(u) : "f"(f));
    return __uint_as_float(u);
}
__device__ __forceinline__ unsigned fau(float f) { return __float_as_uint(f); }

__device__ __forceinline__ void mma8(float* c, const unsigned* a, unsigned b0, unsigned b1) {
    asm("mma.sync.aligned.m16n8k8.row.col.f32.tf32.tf32.f32 "
        "{%0,%1,%2,%3}, {%4,%5,%6,%7}, {%8,%9}, {%0,%1,%2,%3};"
        : "+f"(c[0]), "+f"(c[1]), "+f"(c[2]), "+f"(c[3])
        : "r"(a[0]), "r"(a[1]), "r"(a[2]), "r"(a[3]), "r"(b0), "r"(b1));
}
#define CPA16(d, s) asm volatile("cp.async.ca.shared.global [%0], [%1], 16;" :: "r"(d), "l"(s))
#define CPA_COMMIT() asm volatile("cp.async.commit_group;" ::: "memory")
#define CPA_WAIT1()  asm volatile("cp.async.wait_group 1;" ::: "memory")
#define CPA_WAIT0()  asm volatile("cp.async.wait_group 0;" ::: "memory")

// ============ prep: per-batch threshold t (+ W1^T images in first 52 CTAs) ====
__global__ __launch_bounds__(512)
void prep_kernel(const float* __restrict__ x, const float* __restrict__ W1)
{
    const int b   = blockIdx.x;
    const int tid = threadIdx.x;
    const float* __restrict__ xb = x + (size_t)b * N * N;

    // fold in W1^T chunk-image build (52 CTAs x 512 = 26624 elements)
    if (b < 52) {
        int idx = b * 512 + tid;
        int c   = idx >> 11;           // /2048
        int rst = idx & 2047;
        int hh  = rst >> 10;
        int hl  = (rst >> 4) & 63;
        int kk  = idx & 15;
        int k = c * 16 + kk, h = hh * 64 + hl;
        g_w1t[idx] = (k < N) ? tf32r(W1[k * H + h]) : 0.f;
    }

    __shared__ unsigned int hist[NBINS];
    __shared__ float cand[MAXCAND];
    __shared__ float t_sh;
    __shared__ int binB_sh, r_sh, cnt_sh;

    for (int i = tid; i < NBINS; i += 512) hist[i] = 0u;
    __syncthreads();

    for (int e = tid; e < N * N; e += 512) {
        float vv = xb[e];
        int bin = (int)(vv * 4096.0f);
        bin = min(max(bin, 0), NBINS - 1);
        atomicAdd(&hist[bin], 1u);
    }
    __syncthreads();

    if (tid == 0) {
        int acc = 0, bsel = 0, r = 1;
        for (int bi = NBINS - 1; bi >= 0; --bi) {
            int nacc = acc + (int)hist[bi];
            if (nacc >= K_TOP) { bsel = bi; r = K_TOP - acc; break; }
            acc = nacc;
        }
        binB_sh = bsel; r_sh = r; cnt_sh = 0;
        t_sh = (float)bsel / 4096.0f;    // fallback, never expected
    }
    __syncthreads();

    const int binB = binB_sh;
    for (int e = tid; e < N * N; e += 512) {
        float vv = xb[e];
        int bin = (int)(vv * 4096.0f);
        bin = min(max(bin, 0), NBINS - 1);
        if (bin == binB) {
            int p = atomicAdd(&cnt_sh, 1);
            if (p < MAXCAND) cand[p] = vv;
        }
    }
    __syncthreads();

    {
        const int m = min(cnt_sh, MAXCAND);
        const int r = r_sh;
        for (int ci = tid; ci < m; ci += 512) {
            float vv = cand[ci];
            int gg = 0, eq = 0;
            for (int l = 0; l < m; ++l) {
                float c = cand[l];
                gg += (c > vv);
                eq += (c == vv);
            }
            if (gg < r && gg + eq >= r) t_sh = vv;
        }
    }
    __syncthreads();
    if (tid == 0) g_t[b] = t_sh;
}

// ============ main: per (batch, h-half) fused kernel, 2 CTAs/SM ============
extern __shared__ float sm[];

__global__ __launch_bounds__(256, 2)
void main_kernel(const float* __restrict__ x, const float* __restrict__ b1)
{
    const int b    = blockIdx.x >> 1;
    const int hh   = blockIdx.x & 1;
    const int tid  = threadIdx.x;
    const int warp = tid >> 5;
    const int lane = tid & 31;
    const int g    = lane >> 2;       // 0..7
    const int tig  = lane & 3;        // 0..3
    const float* __restrict__ xb = x + (size_t)b * N * N;

    float* Yt     = sm + YT_O;
    float* dinv_s = sm + DINV_O;      // deg first, then dinv in place
    float* u_s    = sm + U_O;         // rowdot first, then u in place
    float* b1_s   = sm + B1_O;
    float* vacc   = sm + VACC_O;
    const unsigned shb = (unsigned)__cvta_generic_to_shared(sm);

    if (tid < 208) { dinv_s[tid] = 0.f; u_s[tid] = 0.f; }
    if (tid < 64)  { b1_s[tid] = b1[hh * 64 + tid]; vacc[tid] = 0.f; }
    const float t = g_t[b];
    __syncthreads();

    // warp tiling: mw = m-pair (2 m16-tiles), nq = n-quarter (7 n-tiles)
    const int mw  = warp & 1;
    const int nq  = warp >> 1;        // 0..3
    const int m0  = mw * 32;
    const int nlo = nq * 7;           // tiles nlo..nlo+6, guard nt<25

    // ---------------- GEMM1: D1[h(64)][i(200)] = W1t_half @ X^T ------------
    auto stage1 = [&](int c, int buf) {
        const unsigned swd = shb + (buf ? SW1_O : SW0_O) * 4;
        const unsigned sbd = shb + (buf ? SB1_O : SB0_O) * 4;
        const float* wsrc = g_w1t + (c * 2 + hh) * 1024;
        {   // W1t chunk [64][16] -> stride 20
            int hl = tid >> 2, q = tid & 3;
            CPA16(swd + hl * 80 + q * 16, wsrc + hl * 16 + q * 4);
        }
        const int kc = c * 16;
        if (c < NCH - 1) {            // x rows [200][16]
            for (int idx = tid; idx < 800; idx += 256) {
                int i = idx >> 2, q = idx & 3;
                CPA16(sbd + i * 80 + q * 16, xb + i * N + kc + q * 4);
            }
        } else {                      // last: [200][8]
            for (int idx = tid; idx < 400; idx += 256) {
                int i = idx >> 1, q = idx & 1;
                CPA16(sbd + i * 80 + q * 16, xb + i * N + kc + q * 4);
            }
        }
    };

    float C1[2][7][4];
    #pragma unroll
    for (int mt = 0; mt < 2; ++mt)
        #pragma unroll
        for (int idx = 0; idx < 7; ++idx)
            #pragma unroll
            for (int q = 0; q < 4; ++q) C1[mt][idx][q] = 0.f;

    stage1(0, 0);
    CPA_COMMIT();
    for (int c = 0; c < NCH; ++c) {
        if (c < NCH - 1) { stage1(c + 1, (c + 1) & 1); CPA_COMMIT(); CPA_WAIT1(); }
        else             { CPA_WAIT0(); }
        __syncthreads();
        const float* bs = sm + ((c & 1) ? SB1_O : SB0_O);
        const float* ws = sm + ((c & 1) ? SW1_O : SW0_O);
        const int kw  = (c < NCH - 1) ? 16 : 8;
        const int kst = (c < NCH - 1) ? 2 : 1;
        for (int ks = 0; ks < kst; ++ks) {
            const int kk0 = ks * 8 + tig;
            unsigned a[2][4];
            #pragma unroll
            for (int mt = 0; mt < 2; ++mt) {
                int r = m0 + 16 * mt + g;
                a[mt][0] = fau(ws[r * S1_STR + kk0]);
                a[mt][1] = fau(ws[(r + 8) * S1_STR + kk0]);
                a[mt][2] = fau(ws[r * S1_STR + kk0 + 4]);
                a[mt][3] = fau(ws[(r + 8) * S1_STR + kk0 + 4]);
            }
            #pragma unroll
            for (int idx = 0; idx < 7; ++idx) {
                int nt = nlo + idx;
                if (nt < 25) {
                    int row = nt * 8 + g;
                    unsigned b0 = fau(bs[row * S1_STR + kk0]);
                    unsigned bq = fau(bs[row * S1_STR + kk0 + 4]);
                    mma8(C1[0][idx], a[0], b0, bq);
                    mma8(C1[1][idx], a[1], b0, bq);
                }
            }
        }
        // deg: masked column sums of this col-block
        {
            const int colL = tid >> 4, part = tid & 15;   // 16 cols x 16 parts
            if (colL < kw) {
                float s = 0.f;
                const int i0 = part * 13;
                const int ie = min(i0 + 13, N);
                for (int i = i0; i < ie; ++i) {
                    float v = bs[i * S1_STR + colL];
                    s += (v >= t) ? v : 0.f;
                }
                s += __shfl_xor_sync(0xffffffffu, s, 1);
                s += __shfl_xor_sync(0xffffffffu, s, 2);
                s += __shfl_xor_sync(0xffffffffu, s, 4);
                s += __shfl_xor_sync(0xffffffffu, s, 8);
                if (part == 0) dinv_s[c * 16 + colL] += s;
            }
        }
        __syncthreads();
    }

    // deg -> dinv (in place)
    if (tid < 208) dinv_s[tid] = (tid < N) ? rsqrtf(1.0f + dinv_s[tid]) : 0.f;
    __syncthreads();

    // Epilogue 1: Yt[h_local][i] = tf32(dinv_i * D1)
    #pragma unroll
    for (int mt = 0; mt < 2; ++mt) {
        int h = m0 + 16 * mt + g;
        #pragma unroll
        for (int idx = 0; idx < 7; ++idx) {
            int nt = nlo + idx;
            if (nt < 25) {
                int i0 = nt * 8 + tig * 2;
                float d0 = dinv_s[i0], d1 = dinv_s[i0 + 1];
                float2 lo = make_float2(tf32r(C1[mt][idx][0] * d0), tf32r(C1[mt][idx][1] * d1));
                float2 hi = make_float2(tf32r(C1[mt][idx][2] * d0), tf32r(C1[mt][idx][3] * d1));
                *(float2*)&Yt[h * YT_STR + i0]       = lo;
                *(float2*)&Yt[(h + 8) * YT_STR + i0] = hi;
            }
        }
    }

    // ---------------- GEMM2: D2[h(64)][j(200)] = Yt @ (Am + I) -------------
    auto stage2 = [&](int c, int buf) {
        const int kc = c * 16;
        const unsigned sbd = shb + (buf ? SB1_O : SB0_O) * 4;
        const int nrows = (c < NCH - 1) ? 16 : 8;
        for (int idx = tid; idx < nrows * 50; idx += 256) {
            int i = idx / 50, q = idx - i * 50;
            CPA16(sbd + i * (G2_STR * 4) + q * 16, xb + (size_t)(kc + i) * N + q * 4);
        }
    };

    float C2[2][7][4];
    #pragma unroll
    for (int mt = 0; mt < 2; ++mt)
        #pragma unroll
        for (int idx = 0; idx < 7; ++idx)
            #pragma unroll
            for (int q = 0; q < 4; ++q) C2[mt][idx][q] = 0.f;

    stage2(0, 0);
    CPA_COMMIT();
    for (int c = 0; c < NCH; ++c) {
        if (c < NCH - 1) { stage2(c + 1, (c + 1) & 1); CPA_COMMIT(); CPA_WAIT1(); }
        else             { CPA_WAIT0(); }
        __syncthreads();
        float* bs = sm + ((c & 1) ? SB1_O : SB0_O);
        const int kc    = c * 16;
        const int nrows = (c < NCH - 1) ? 16 : 8;
        // mask (>= t), +I diagonal, tf32-round in place; accumulate u rowdots
        {
            const int il = tid >> 4, part = tid & 15;   // 16 rows x 16 parts
            float s = 0.f;
            if (il < nrows) {
                const int gi = kc + il;
                float* row = bs + il * G2_STR;
                const int j0 = part * 13;
                const int je = min(j0 + 13, N);
                for (int j = j0; j < je; ++j) {
                    float v = row[j];
                    v = (v >= t) ? v : 0.f;
                    if (j == gi) v += 1.0f;
                    v = tf32r(v);
                    row[j] = v;
                    s += v * dinv_s[j];
                }
            }
            s += __shfl_xor_sync(0xffffffffu, s, 1);
            s += __shfl_xor_sync(0xffffffffu, s, 2);
            s += __shfl_xor_sync(0xffffffffu, s, 4);
            s += __shfl_xor_sync(0xffffffffu, s, 8);
            if (part == 0 && il < nrows) u_s[kc + il] = s;
        }
        __syncthreads();
        const int kst = (c < NCH - 1) ? 2 : 1;
        for (int ks = 0; ks < kst; ++ks) {
            const int kk0 = ks * 8 + tig;
            unsigned a[2][4];
            #pragma unroll
            for (int mt = 0; mt < 2; ++mt) {
                int r = m0 + 16 * mt + g;
                a[mt][0] = fau(Yt[r * YT_STR + kc + kk0]);
                a[mt][1] = fau(Yt[(r + 8) * YT_STR + kc + kk0]);
                a[mt][2] = fau(Yt[r * YT_STR + kc + kk0 + 4]);
                a[mt][3] = fau(Yt[(r + 8) * YT_STR + kc + kk0 + 4]);
            }
            #pragma unroll
            for (int idx = 0; idx < 7; ++idx) {
                int nt = nlo + idx;
                if (nt < 25) {
                    int col = nt * 8 + g;
                    unsigned b0 = fau(bs[kk0 * G2_STR + col]);
                    unsigned bq = fau(bs[(kk0 + 4) * G2_STR + col]);
                    mma8(C2[0][idx], a[0], b0, bq);
                    mma8(C2[1][idx], a[1], b0, bq);
                }
            }
        }
        __syncthreads();
    }

    // finalize u: u_j = dinv_j * rowdot_j
    if (tid < 208) u_s[tid] = (tid < N) ? dinv_s[tid] * u_s[tid] : 0.f;
    __syncthreads();

    // Epilogue 2: h1 = relu(dinv_j * D2 + b1_h); v_h += u_j * h1
    float sAcc[2][2] = {{0.f, 0.f}, {0.f, 0.f}};
    #pragma unroll
    for (int mt = 0; mt < 2; ++mt) {
        int h = m0 + 16 * mt + g;
        float bl = b1_s[h], bh = b1_s[h + 8];
        #pragma unroll
        for (int idx = 0; idx < 7; ++idx) {
            int nt = nlo + idx;
            if (nt < 25) {
                int j0 = nt * 8 + tig * 2;
                int j1 = j0 + 1;
                float d0 = dinv_s[j0], d1 = dinv_s[j1];
                float u0 = u_s[j0],    u1 = u_s[j1];
                sAcc[mt][0] += u0 * fmaxf(fmaf(d0, C2[mt][idx][0], bl), 0.f)
                             + u1 * fmaxf(fmaf(d1, C2[mt][idx][1], bl), 0.f);
                sAcc[mt][1] += u0 * fmaxf(fmaf(d0, C2[mt][idx][2], bh), 0.f)
                             + u1 * fmaxf(fmaf(d1, C2[mt][idx][3], bh), 0.f);
            }
        }
    }
    #pragma unroll
    for (int mt = 0; mt < 2; ++mt)
        #pragma unroll
        for (int hf = 0; hf < 2; ++hf) {
            float s = sAcc[mt][hf];
            s += __shfl_xor_sync(0xffffffffu, s, 1);
            s += __shfl_xor_sync(0xffffffffu, s, 2);
            sAcc[mt][hf] = s;
        }
    if (tig == 0) {
        atomicAdd(&vacc[m0 + g],      sAcc[0][0]);
        atomicAdd(&vacc[m0 + 8 + g],  sAcc[0][1]);
        atomicAdd(&vacc[m0 + 16 + g], sAcc[1][0]);
        atomicAdd(&vacc[m0 + 24 + g], sAcc[1][1]);
    }
    __syncthreads();

    // publish this half of v
    if (tid < 64) g_v[b * H + hh * 64 + tid] = vacc[tid];
}

// res[b][h] = (1/N) * sum_f v[b][f] * W2[f][h] + b2[h]
__global__ __launch_bounds__(256)
void final_kernel(const float* __restrict__ W2,
                  const float* __restrict__ b2,
                  float* __restrict__ out)
{
    __shared__ float v_s[2][H];
    const int tid = threadIdx.x;
    const int b0  = blockIdx.x * 2;
    v_s[tid >> 7][tid & 127] = g_v[b0 * H + tid];
    __syncthreads();
    const int bb = tid >> 7;
    const int h  = tid & 127;
    float acc = 0.f;
    #pragma unroll 8
    for (int f = 0; f < H; ++f)
        acc += v_s[bb][f] * W2[f * H + h];
    out[(b0 + bb) * H + h] = acc * (1.0f / (float)N) + b2[h];
}

extern "C" void kernel_launch(void* const* d_in, const int* in_sizes, int n_in,
                              void* d_out, int out_size)
{
    const float* x  = (const float*)d_in[0];
    // d_in[1] = adj : unused (overwritten by sparse(x,0.2) in the reference)
    const float* W1 = (const float*)d_in[2];
    const float* b1 = (const float*)d_in[3];
    const float* W2 = (const float*)d_in[4];
    const float* b2 = (const float*)d_in[5];
    float* out = (float*)d_out;

    cudaFuncSetAttribute(main_kernel,
                         cudaFuncAttributeMaxDynamicSharedMemorySize,
                         SMEM_FLOATS * (int)sizeof(float));

    prep_kernel<<<BATCH, 512>>>(x, W1);                                       // launch 1
    main_kernel<<<2 * BATCH, 256, SMEM_FLOATS * sizeof(float)>>>(x, b1);      // launch 2
    final_kernel<<<BATCH / 2, 256>>>(W2, b2, out);                            // launch 3
}